// round 4
// baseline (speedup 1.0000x reference)
#include <cuda_runtime.h>

#define Bb 64
#define Tt 512
#define Ii 256
#define Hh 512
#define Mm (Bb*Tt)   // 32768 rows

__device__ __align__(16) float g_W1[Hh*Ii];
__device__ __align__(16) float g_W2[Hh*Hh];
__device__ __align__(16) float g_z1[Mm*Hh];
__device__ __align__(16) float g_s1[Mm*Hh];
__device__ __align__(16) float g_y2[Mm*Hh];

// ---- packed fp32x2 helpers (Blackwell) ----
__device__ __forceinline__ unsigned long long f32x2_fma(
    unsigned long long a, unsigned long long b, unsigned long long c) {
    unsigned long long d;
    asm("fma.rn.f32x2 %0, %1, %2, %3;" : "=l"(d) : "l"(a), "l"(b), "l"(c));
    return d;
}
__device__ __forceinline__ unsigned long long fdup(float x) {
    unsigned long long d;
    asm("mov.b64 %0, {%1, %2};" : "=l"(d) : "f"(x), "f"(x));
    return d;
}
__device__ __forceinline__ float2 funpack(unsigned long long v) {
    float lo, hi;
    asm("mov.b64 {%0, %1}, %2;" : "=f"(lo), "=f"(hi) : "l"(v));
    return make_float2(lo, hi);
}

// -------- extract center tap: W[h,i] = conv_w[h,i,1] --------
__global__ void extract1_k(const float* __restrict__ src) {
    int i = blockIdx.x * blockDim.x + threadIdx.x;
    if (i < Hh*Ii) g_W1[i] = src[i*3 + 1];
}
__global__ void extract2_k(const float* __restrict__ src) {
    int i = blockIdx.x * blockDim.x + threadIdx.x;
    if (i < Hh*Hh) g_W2[i] = src[i*3 + 1];
}

// -------- SGEMM: C[M,512] = A[M,K] * B[512,K]^T (+bias) --------
// 128x128 tile, 256 threads, 8x8 per thread via packed f32x2 (pairs over N).
// A stored DUPLICATED in smem ({a,a} 64-bit pairs) so the broadcast operand
// loads as pairs with no per-k pack instructions.
// Each acc component: single fp32 accumulator, ascending k — bitwise identical
// to scalar FFMA GEMM (fma.rn.f32x2 = 2 independent IEEE-RN fp32 FMAs).
template<int K, bool ADD_BIAS>
__device__ __forceinline__ void sgemm128(
    const float* __restrict__ A, const float* __restrict__ Bm,
    const float* __restrict__ bias, float* __restrict__ C)
{
    __shared__ __align__(16) float As2[2][8][264];   // duplicated pairs: col 2r, 2r+1
    __shared__ __align__(16) float Bs[2][8][132];

    const int tid = threadIdx.x;
    const int tx  = tid & 15;          // n: 16*8 = 128
    const int ty  = tid >> 4;          // m: 16*8 = 128
    const int m0  = blockIdx.y * 128;
    const int n0  = blockIdx.x * 128;

    const int lr = tid >> 1;           // 0..127
    const int lc = (tid & 1) * 4;      // 0 or 4
    const float* Ap = A  + (size_t)(m0 + lr) * K + lc;
    const float* Bp = Bm + (size_t)(n0 + lr) * K + lc;

    float4 a4 = *(const float4*)Ap;
    float4 b4 = *(const float4*)Bp;
    *(unsigned long long*)&As2[0][lc+0][2*lr] = fdup(a4.x);
    *(unsigned long long*)&As2[0][lc+1][2*lr] = fdup(a4.y);
    *(unsigned long long*)&As2[0][lc+2][2*lr] = fdup(a4.z);
    *(unsigned long long*)&As2[0][lc+3][2*lr] = fdup(a4.w);
    Bs[0][lc+0][lr]=b4.x; Bs[0][lc+1][lr]=b4.y; Bs[0][lc+2][lr]=b4.z; Bs[0][lc+3][lr]=b4.w;
    __syncthreads();

    unsigned long long acc2[8][4];
    #pragma unroll
    for (int i = 0; i < 8; i++)
        #pragma unroll
        for (int j = 0; j < 4; j++) acc2[i][j] = 0ull;

    int p = 0;
    for (int k0 = 8; k0 <= K; k0 += 8) {
        const bool more = (k0 < K);
        if (more) { a4 = *(const float4*)(Ap + k0); b4 = *(const float4*)(Bp + k0); }

        #pragma unroll
        for (int k = 0; k < 8; k++) {
            unsigned long long rap[8], rbp[4];
            {
                const ulonglong2* ap = (const ulonglong2*)&As2[p][k][ty*16];
                ulonglong2 t0 = ap[0], t1 = ap[1], t2 = ap[2], t3 = ap[3];
                rap[0]=t0.x; rap[1]=t0.y; rap[2]=t1.x; rap[3]=t1.y;
                rap[4]=t2.x; rap[5]=t2.y; rap[6]=t3.x; rap[7]=t3.y;
            }
            {
                const ulonglong2* bp = (const ulonglong2*)&Bs[p][k][tx*8];
                ulonglong2 t0 = bp[0], t1 = bp[1];
                rbp[0]=t0.x; rbp[1]=t0.y; rbp[2]=t1.x; rbp[3]=t1.y;
            }
            #pragma unroll
            for (int i = 0; i < 8; i++)
                #pragma unroll
                for (int j = 0; j < 4; j++)
                    acc2[i][j] = f32x2_fma(rap[i], rbp[j], acc2[i][j]);
        }

        if (more) {
            const int q = p ^ 1;
            *(unsigned long long*)&As2[q][lc+0][2*lr] = fdup(a4.x);
            *(unsigned long long*)&As2[q][lc+1][2*lr] = fdup(a4.y);
            *(unsigned long long*)&As2[q][lc+2][2*lr] = fdup(a4.z);
            *(unsigned long long*)&As2[q][lc+3][2*lr] = fdup(a4.w);
            Bs[q][lc+0][lr]=b4.x; Bs[q][lc+1][lr]=b4.y; Bs[q][lc+2][lr]=b4.z; Bs[q][lc+3][lr]=b4.w;
            __syncthreads();
            p = q;
        }
    }

    #pragma unroll
    for (int i = 0; i < 8; i++) {
        const int m = m0 + ty*8 + i;
        float v[8];
        #pragma unroll
        for (int j = 0; j < 4; j++) {
            float2 u = funpack(acc2[i][j]);
            v[2*j] = u.x; v[2*j+1] = u.y;
        }
        if (ADD_BIAS) {
            const int n = n0 + tx*8;
            #pragma unroll
            for (int j = 0; j < 8; j++) v[j] += bias[n+j];
        }
        float* cp = C + (size_t)m * Hh + n0 + tx*8;
        float4 v0 = make_float4(v[0],v[1],v[2],v[3]);
        float4 v1 = make_float4(v[4],v[5],v[6],v[7]);
        *(float4*)cp       = v0;
        *(float4*)(cp + 4) = v1;
    }
}

__global__ void __launch_bounds__(256, 2) sgemm1_k(const float* __restrict__ A,
                                                   const float* __restrict__ bias) {
    sgemm128<Ii, true>(A, g_W1, bias, g_z1);
}
__global__ void __launch_bounds__(256, 2) sgemm2_k() {
    sgemm128<Hh, false>(g_s1, g_W2, nullptr, g_y2);
}

// -------- LIF scans: 32768 independent chains over T=512 --------
#define SCH 16   // prefetch chunk depth

template<bool BIAS_EACH_STEP>
__device__ __forceinline__ void scan_body(const float* __restrict__ Z,
                                          float* __restrict__ S,
                                          const float th, const float bi)
{
    const int idx = blockIdx.x * blockDim.x + threadIdx.x;   // 0..32767
    const int b = idx >> 9;
    const int h = idx & 511;
    const float inv = 1.0f / th;
    const float* zp = Z + (size_t)b * Tt * Hh + h;
    float*       sp = S + (size_t)b * Tt * Hh + h;

    float cur[SCH], nxt[SCH];
    #pragma unroll
    for (int u = 0; u < SCH; u++) cur[u] = zp[(size_t)u * Hh];

    float m = 0.f;
    for (int t0 = 0; t0 < Tt; t0 += SCH) {
        if (t0 + SCH < Tt) {
            #pragma unroll
            for (int u = 0; u < SCH; u++) nxt[u] = zp[(size_t)(t0 + SCH + u) * Hh];
        }
        #pragma unroll
        for (int u = 0; u < SCH; u++) {
            if (BIAS_EACH_STEP) m = (m + cur[u]) + bi;   // ((m + dot) + b) ref order
            else                m = m + cur[u];
            const float thr = __fmaf_rn(m, inv, -1.0f);
            sp[(size_t)(t0 + u) * Hh] = (thr >= 0.0f) ? 1.0f : 0.0f;
            m = (thr > 0.0f) ? (m - th) : m;             // branchless
        }
        #pragma unroll
        for (int u = 0; u < SCH; u++) cur[u] = nxt[u];
    }
}

__global__ void __launch_bounds__(64) scan1_k(const float* __restrict__ th_p) {
    scan_body<false>(g_z1, g_s1, *th_p, 0.f);
}
__global__ void __launch_bounds__(64) scan2_k(const float* __restrict__ th_p,
                                              const float* __restrict__ bias,
                                              float* __restrict__ out) {
    const int idx = blockIdx.x * blockDim.x + threadIdx.x;
    scan_body<true>(g_y2, out, *th_p, bias[idx & 511]);
}

extern "C" void kernel_launch(void* const* d_in, const int* in_sizes, int n_in,
                              void* d_out, int out_size)
{
    const float* x   = (const float*)d_in[0];
    const float* c1w = (const float*)d_in[1];
    const float* c1b = (const float*)d_in[2];
    const float* c2w = (const float*)d_in[3];
    const float* c2b = (const float*)d_in[4];
    const float* th1 = (const float*)d_in[5];
    const float* th2 = (const float*)d_in[6];
    float* out = (float*)d_out;

    extract1_k<<<(Hh*Ii + 255)/256, 256>>>(c1w);
    extract2_k<<<(Hh*Hh + 255)/256, 256>>>(c2w);

    dim3 g1(Hh/128, Mm/128);              // (4, 256)
    sgemm1_k<<<g1, 256>>>(x, c1b);
    scan1_k<<<Mm/64, 64>>>(th1);
    sgemm2_k<<<g1, 256>>>();
    scan2_k<<<Mm/64, 64>>>(th2, c2b, out);
}

// round 5
// speedup vs baseline: 1.1474x; 1.1474x over previous
#include <cuda_runtime.h>

#define Bb 64
#define Tt 512
#define Ii 256
#define Hh 512
#define Mm (Bb*Tt)   // 32768 rows

__device__ __align__(16) float g_W1[Hh*Ii];
__device__ __align__(16) float g_W2[Hh*Hh];
__device__ __align__(16) float g_z1[Mm*Hh];
__device__ __align__(16) float g_s1[Mm*Hh];
__device__ __align__(16) float g_y2[Mm*Hh];

// ---- packed fp32x2 helpers (Blackwell) ----
__device__ __forceinline__ unsigned long long f32x2_fma(
    unsigned long long a, unsigned long long b, unsigned long long c) {
    unsigned long long d;
    asm("fma.rn.f32x2 %0, %1, %2, %3;" : "=l"(d) : "l"(a), "l"(b), "l"(c));
    return d;
}
__device__ __forceinline__ unsigned long long fdup(float x) {
    unsigned long long d;
    asm("mov.b64 %0, {%1, %2};" : "=l"(d) : "f"(x), "f"(x));
    return d;
}
__device__ __forceinline__ float2 funpack(unsigned long long v) {
    float lo, hi;
    asm("mov.b64 {%0, %1}, %2;" : "=f"(lo), "=f"(hi) : "l"(v));
    return make_float2(lo, hi);
}

// -------- extract center tap: W[h,i] = conv_w[h,i,1] --------
__global__ void extract1_k(const float* __restrict__ src) {
    int i = blockIdx.x * blockDim.x + threadIdx.x;
    if (i < Hh*Ii) g_W1[i] = src[i*3 + 1];
}
__global__ void extract2_k(const float* __restrict__ src) {
    int i = blockIdx.x * blockDim.x + threadIdx.x;
    if (i < Hh*Hh) g_W2[i] = src[i*3 + 1];
}

// ======== Scalar SGEMM (R3-proven): C = A*B^T (+bias) ========
// 128x128 tile, 256 threads, 8x8/thread, double-buffered smem.
template<int K, bool ADD_BIAS>
__device__ __forceinline__ void sgemm128(
    const float* __restrict__ A, const float* __restrict__ Bm,
    const float* __restrict__ bias, float* __restrict__ C)
{
    __shared__ float As[2][8][132];
    __shared__ float Bs[2][8][132];

    const int tid = threadIdx.x;
    const int tx  = tid & 15;
    const int ty  = tid >> 4;
    const int m0  = blockIdx.y * 128;
    const int n0  = blockIdx.x * 128;

    const int lr = tid >> 1;
    const int lc = (tid & 1) * 4;
    const float* Ap = A  + (size_t)(m0 + lr) * K + lc;
    const float* Bp = Bm + (size_t)(n0 + lr) * K + lc;

    float4 a4 = *(const float4*)Ap;
    float4 b4 = *(const float4*)Bp;
    As[0][lc+0][lr]=a4.x; As[0][lc+1][lr]=a4.y; As[0][lc+2][lr]=a4.z; As[0][lc+3][lr]=a4.w;
    Bs[0][lc+0][lr]=b4.x; Bs[0][lc+1][lr]=b4.y; Bs[0][lc+2][lr]=b4.z; Bs[0][lc+3][lr]=b4.w;
    __syncthreads();

    float acc[8][8];
    #pragma unroll
    for (int i = 0; i < 8; i++)
        #pragma unroll
        for (int j = 0; j < 8; j++) acc[i][j] = 0.f;

    int p = 0;
    for (int k0 = 8; k0 <= K; k0 += 8) {
        const bool more = (k0 < K);
        if (more) { a4 = *(const float4*)(Ap + k0); b4 = *(const float4*)(Bp + k0); }

        #pragma unroll
        for (int k = 0; k < 8; k++) {
            float ra[8], rb[8];
            *(float4*)&ra[0] = *(const float4*)&As[p][k][ty*8];
            *(float4*)&ra[4] = *(const float4*)&As[p][k][ty*8+4];
            *(float4*)&rb[0] = *(const float4*)&Bs[p][k][tx*8];
            *(float4*)&rb[4] = *(const float4*)&Bs[p][k][tx*8+4];
            #pragma unroll
            for (int i = 0; i < 8; i++)
                #pragma unroll
                for (int j = 0; j < 8; j++)
                    acc[i][j] = __fmaf_rn(ra[i], rb[j], acc[i][j]);
        }

        if (more) {
            const int q = p ^ 1;
            As[q][lc+0][lr]=a4.x; As[q][lc+1][lr]=a4.y; As[q][lc+2][lr]=a4.z; As[q][lc+3][lr]=a4.w;
            Bs[q][lc+0][lr]=b4.x; Bs[q][lc+1][lr]=b4.y; Bs[q][lc+2][lr]=b4.z; Bs[q][lc+3][lr]=b4.w;
            __syncthreads();
            p = q;
        }
    }

    #pragma unroll
    for (int i = 0; i < 8; i++) {
        const int m = m0 + ty*8 + i;
        float4 v0, v1;
        v0.x=acc[i][0]; v0.y=acc[i][1]; v0.z=acc[i][2]; v0.w=acc[i][3];
        v1.x=acc[i][4]; v1.y=acc[i][5]; v1.z=acc[i][6]; v1.w=acc[i][7];
        if (ADD_BIAS) {
            const int n = n0 + tx*8;
            v0.x+=bias[n+0]; v0.y+=bias[n+1]; v0.z+=bias[n+2]; v0.w+=bias[n+3];
            v1.x+=bias[n+4]; v1.y+=bias[n+5]; v1.z+=bias[n+6]; v1.w+=bias[n+7];
        }
        float* cp = C + (size_t)m * Hh + n0 + tx*8;
        *(float4*)cp       = v0;
        *(float4*)(cp + 4) = v1;
    }
}

// ======== FFMA2 SGEMM (experiment, GEMM2 only) ========
// Identical memory layout/loads to scalar version (A scalar in smem,
// 4x LDS.128 per k). Pairs over N: rbp = natural 64-bit pairs from Bs,
// A dup'd per-i in registers via one mov.b64. Each f32x2 lane is an
// independent IEEE-RN FMA; per-accumulator ascending-k order unchanged
// -> bitwise identical to the scalar GEMM.
template<int K>
__device__ __forceinline__ void sgemm128_x2(
    const float* __restrict__ A, const float* __restrict__ Bm,
    float* __restrict__ C)
{
    __shared__ float As[2][8][132];
    __shared__ float Bs[2][8][132];

    const int tid = threadIdx.x;
    const int tx  = tid & 15;
    const int ty  = tid >> 4;
    const int m0  = blockIdx.y * 128;
    const int n0  = blockIdx.x * 128;

    const int lr = tid >> 1;
    const int lc = (tid & 1) * 4;
    const float* Ap = A  + (size_t)(m0 + lr) * K + lc;
    const float* Bp = Bm + (size_t)(n0 + lr) * K + lc;

    float4 a4 = *(const float4*)Ap;
    float4 b4 = *(const float4*)Bp;
    As[0][lc+0][lr]=a4.x; As[0][lc+1][lr]=a4.y; As[0][lc+2][lr]=a4.z; As[0][lc+3][lr]=a4.w;
    Bs[0][lc+0][lr]=b4.x; Bs[0][lc+1][lr]=b4.y; Bs[0][lc+2][lr]=b4.z; Bs[0][lc+3][lr]=b4.w;
    __syncthreads();

    unsigned long long acc2[8][4];   // 64 regs, same as scalar acc[8][8]
    #pragma unroll
    for (int i = 0; i < 8; i++)
        #pragma unroll
        for (int j = 0; j < 4; j++) acc2[i][j] = 0ull;

    int p = 0;
    for (int k0 = 8; k0 <= K; k0 += 8) {
        const bool more = (k0 < K);
        if (more) { a4 = *(const float4*)(Ap + k0); b4 = *(const float4*)(Bp + k0); }

        #pragma unroll
        for (int k = 0; k < 8; k++) {
            float ra[8];
            *(float4*)&ra[0] = *(const float4*)&As[p][k][ty*8];
            *(float4*)&ra[4] = *(const float4*)&As[p][k][ty*8+4];
            unsigned long long rbp[4];
            {
                const ulonglong2* bp = (const ulonglong2*)&Bs[p][k][tx*8];
                ulonglong2 t0 = bp[0], t1 = bp[1];
                rbp[0]=t0.x; rbp[1]=t0.y; rbp[2]=t1.x; rbp[3]=t1.y;
            }
            #pragma unroll
            for (int i = 0; i < 8; i++) {
                const unsigned long long ad = fdup(ra[i]);
                #pragma unroll
                for (int j = 0; j < 4; j++)
                    acc2[i][j] = f32x2_fma(ad, rbp[j], acc2[i][j]);
            }
        }

        if (more) {
            const int q = p ^ 1;
            As[q][lc+0][lr]=a4.x; As[q][lc+1][lr]=a4.y; As[q][lc+2][lr]=a4.z; As[q][lc+3][lr]=a4.w;
            Bs[q][lc+0][lr]=b4.x; Bs[q][lc+1][lr]=b4.y; Bs[q][lc+2][lr]=b4.z; Bs[q][lc+3][lr]=b4.w;
            __syncthreads();
            p = q;
        }
    }

    #pragma unroll
    for (int i = 0; i < 8; i++) {
        const int m = m0 + ty*8 + i;
        float2 u0 = funpack(acc2[i][0]);
        float2 u1 = funpack(acc2[i][1]);
        float2 u2 = funpack(acc2[i][2]);
        float2 u3 = funpack(acc2[i][3]);
        float4 v0 = make_float4(u0.x, u0.y, u1.x, u1.y);
        float4 v1 = make_float4(u2.x, u2.y, u3.x, u3.y);
        float* cp = C + (size_t)m * Hh + n0 + tx*8;
        *(float4*)cp       = v0;
        *(float4*)(cp + 4) = v1;
    }
}

__global__ void __launch_bounds__(256, 2) sgemm1_k(const float* __restrict__ A,
                                                   const float* __restrict__ bias) {
    sgemm128<Ii, true>(A, g_W1, bias, g_z1);
}
__global__ void __launch_bounds__(256, 2) sgemm2_k() {
    sgemm128_x2<Hh>(g_s1, g_W2, g_y2);
}

// -------- LIF scans (R3-proven) --------
#define SCH 16

template<bool BIAS_EACH_STEP>
__device__ __forceinline__ void scan_body(const float* __restrict__ Z,
                                          float* __restrict__ S,
                                          const float th, const float bi)
{
    const int idx = blockIdx.x * blockDim.x + threadIdx.x;
    const int b = idx >> 9;
    const int h = idx & 511;
    const float inv = 1.0f / th;
    const float* zp = Z + (size_t)b * Tt * Hh + h;
    float*       sp = S + (size_t)b * Tt * Hh + h;

    float cur[SCH], nxt[SCH];
    #pragma unroll
    for (int u = 0; u < SCH; u++) cur[u] = zp[(size_t)u * Hh];

    float m = 0.f;
    for (int t0 = 0; t0 < Tt; t0 += SCH) {
        if (t0 + SCH < Tt) {
            #pragma unroll
            for (int u = 0; u < SCH; u++) nxt[u] = zp[(size_t)(t0 + SCH + u) * Hh];
        }
        #pragma unroll
        for (int u = 0; u < SCH; u++) {
            if (BIAS_EACH_STEP) m = (m + cur[u]) + bi;
            else                m = m + cur[u];
            const float thr = __fmaf_rn(m, inv, -1.0f);
            sp[(size_t)(t0 + u) * Hh] = (thr >= 0.0f) ? 1.0f : 0.0f;
            m = (thr > 0.0f) ? (m - th) : m;
        }
        #pragma unroll
        for (int u = 0; u < SCH; u++) cur[u] = nxt[u];
    }
}

__global__ void __launch_bounds__(64) scan1_k(const float* __restrict__ th_p) {
    scan_body<false>(g_z1, g_s1, *th_p, 0.f);
}
__global__ void __launch_bounds__(64) scan2_k(const float* __restrict__ th_p,
                                              const float* __restrict__ bias,
                                              float* __restrict__ out) {
    const int idx = blockIdx.x * blockDim.x + threadIdx.x;
    scan_body<true>(g_y2, out, *th_p, bias[idx & 511]);
}

extern "C" void kernel_launch(void* const* d_in, const int* in_sizes, int n_in,
                              void* d_out, int out_size)
{
    const float* x   = (const float*)d_in[0];
    const float* c1w = (const float*)d_in[1];
    const float* c1b = (const float*)d_in[2];
    const float* c2w = (const float*)d_in[3];
    const float* c2b = (const float*)d_in[4];
    const float* th1 = (const float*)d_in[5];
    const float* th2 = (const float*)d_in[6];
    float* out = (float*)d_out;

    extract1_k<<<(Hh*Ii + 255)/256, 256>>>(c1w);
    extract2_k<<<(Hh*Hh + 255)/256, 256>>>(c2w);

    dim3 g1(Hh/128, Mm/128);              // (4, 256)
    sgemm1_k<<<g1, 256>>>(x, c1b);
    scan1_k<<<Mm/64, 64>>>(th1);
    sgemm2_k<<<g1, 256>>>();
    scan2_k<<<Mm/64, 64>>>(th2, c2b, out);
}

// round 6
// speedup vs baseline: 1.7105x; 1.4907x over previous
#include <cuda_runtime.h>
#include <cstdint>

#define Bb 64
#define Tt 512
#define Ii 256
#define Hh 512
#define Mm (Bb*Tt)   // 32768 rows

__device__ __align__(16) float    g_W1[Hh*Ii];          // 0.5 MB
__device__ __align__(16) float    g_W2T[Hh*Hh];         // 1 MB, [k][n]
__device__ __align__(16) float    g_z1[Mm*Hh];          // 64 MB
__device__ __align__(16) float    g_y2[Mm*Hh];          // 64 MB
__device__ __align__(16) uint32_t g_bits[(Mm/32)*Hh];   // 2 MB, [m>>5][h], bit = m&31
__device__ __align__(16) uint16_t g_list[(size_t)Mm*512]; // 33.5 MB, per-row ascending-k lists
__device__ int g_cnt[Mm];

// -------- extract center tap of conv1: W1[h,i] = conv1_w[h,i,1] --------
__global__ void extract1_k(const float* __restrict__ src) {
    int i = blockIdx.x * blockDim.x + threadIdx.x;
    if (i < Hh*Ii) g_W1[i] = src[i*3 + 1];
}

// -------- transposed extract of conv2: W2T[k][n] = conv2_w[n,k,1] --------
__global__ void extract2t_k(const float* __restrict__ src) {
    __shared__ float tile[32][33];
    const int k0 = blockIdx.x * 32, n0 = blockIdx.y * 32;
    const int tx = threadIdx.x, ty = threadIdx.y;
    tile[ty][tx] = src[((size_t)(n0 + ty) * Hh + (k0 + tx)) * 3 + 1];
    __syncthreads();
    g_W2T[(size_t)(k0 + ty) * Hh + (n0 + tx)] = tile[tx][ty];
}

// ======== Scalar SGEMM (R3-proven): C = A*B^T + bias ========
template<int K>
__device__ __forceinline__ void sgemm128(
    const float* __restrict__ A, const float* __restrict__ Bm,
    const float* __restrict__ bias, float* __restrict__ C)
{
    __shared__ float As[2][8][132];
    __shared__ float Bs[2][8][132];

    const int tid = threadIdx.x;
    const int tx  = tid & 15;
    const int ty  = tid >> 4;
    const int m0  = blockIdx.y * 128;
    const int n0  = blockIdx.x * 128;

    const int lr = tid >> 1;
    const int lc = (tid & 1) * 4;
    const float* Ap = A  + (size_t)(m0 + lr) * K + lc;
    const float* Bp = Bm + (size_t)(n0 + lr) * K + lc;

    float4 a4 = *(const float4*)Ap;
    float4 b4 = *(const float4*)Bp;
    As[0][lc+0][lr]=a4.x; As[0][lc+1][lr]=a4.y; As[0][lc+2][lr]=a4.z; As[0][lc+3][lr]=a4.w;
    Bs[0][lc+0][lr]=b4.x; Bs[0][lc+1][lr]=b4.y; Bs[0][lc+2][lr]=b4.z; Bs[0][lc+3][lr]=b4.w;
    __syncthreads();

    float acc[8][8];
    #pragma unroll
    for (int i = 0; i < 8; i++)
        #pragma unroll
        for (int j = 0; j < 8; j++) acc[i][j] = 0.f;

    int p = 0;
    for (int k0 = 8; k0 <= K; k0 += 8) {
        const bool more = (k0 < K);
        if (more) { a4 = *(const float4*)(Ap + k0); b4 = *(const float4*)(Bp + k0); }

        #pragma unroll
        for (int k = 0; k < 8; k++) {
            float ra[8], rb[8];
            *(float4*)&ra[0] = *(const float4*)&As[p][k][ty*8];
            *(float4*)&ra[4] = *(const float4*)&As[p][k][ty*8+4];
            *(float4*)&rb[0] = *(const float4*)&Bs[p][k][tx*8];
            *(float4*)&rb[4] = *(const float4*)&Bs[p][k][tx*8+4];
            #pragma unroll
            for (int i = 0; i < 8; i++)
                #pragma unroll
                for (int j = 0; j < 8; j++)
                    acc[i][j] = __fmaf_rn(ra[i], rb[j], acc[i][j]);
        }

        if (more) {
            const int q = p ^ 1;
            As[q][lc+0][lr]=a4.x; As[q][lc+1][lr]=a4.y; As[q][lc+2][lr]=a4.z; As[q][lc+3][lr]=a4.w;
            Bs[q][lc+0][lr]=b4.x; Bs[q][lc+1][lr]=b4.y; Bs[q][lc+2][lr]=b4.z; Bs[q][lc+3][lr]=b4.w;
            __syncthreads();
            p = q;
        }
    }

    #pragma unroll
    for (int i = 0; i < 8; i++) {
        const int m = m0 + ty*8 + i;
        float4 v0, v1;
        v0.x=acc[i][0]; v0.y=acc[i][1]; v0.z=acc[i][2]; v0.w=acc[i][3];
        v1.x=acc[i][4]; v1.y=acc[i][5]; v1.z=acc[i][6]; v1.w=acc[i][7];
        const int n = n0 + tx*8;
        v0.x+=bias[n+0]; v0.y+=bias[n+1]; v0.z+=bias[n+2]; v0.w+=bias[n+3];
        v1.x+=bias[n+4]; v1.y+=bias[n+5]; v1.z+=bias[n+6]; v1.w+=bias[n+7];
        float* cp = C + (size_t)m * Hh + n0 + tx*8;
        *(float4*)cp       = v0;
        *(float4*)(cp + 4) = v1;
    }
}

__global__ void __launch_bounds__(256, 2) sgemm1_k(const float* __restrict__ A,
                                                   const float* __restrict__ bias) {
    sgemm128<Ii>(A, g_W1, bias, g_z1);
}

// -------- scan1: LIF over t, emits spike BITS (no fp32 s1) --------
#define SCH 16
__global__ void __launch_bounds__(64) scan1_k(const float* __restrict__ th_p)
{
    const int idx = blockIdx.x * blockDim.x + threadIdx.x;   // (b,h)
    const int b = idx >> 9;
    const int h = idx & 511;
    const float th = *th_p;
    const float inv = 1.0f / th;
    const float* zp = g_z1 + (size_t)b * Tt * Hh + h;
    uint32_t* bp = g_bits + (size_t)b * 16 * Hh + h;         // [b*16 + t/32][h]

    float cur[SCH], nxt[SCH];
    #pragma unroll
    for (int u = 0; u < SCH; u++) cur[u] = zp[(size_t)u * Hh];

    float m = 0.f;
    uint32_t word = 0;
    for (int t0 = 0; t0 < Tt; t0 += SCH) {
        if (t0 + SCH < Tt) {
            #pragma unroll
            for (int u = 0; u < SCH; u++) nxt[u] = zp[(size_t)(t0 + SCH + u) * Hh];
        }
        #pragma unroll
        for (int u = 0; u < SCH; u++) {
            m = m + cur[u];
            const float thr = __fmaf_rn(m, inv, -1.0f);
            const int t = t0 + u;
            if (thr >= 0.0f) word |= (1u << (t & 31));
            m = (thr > 0.0f) ? (m - th) : m;
        }
        if (((t0 + SCH) & 31) == 0) {                        // completed a 32-t word
            bp[((t0 + SCH) >> 5) - 1 ? (((t0 + SCH - 32) >> 5) * Hh) : 0] = word; // see below
            word = 0;
        }
        #pragma unroll
        for (int u = 0; u < SCH; u++) cur[u] = nxt[u];
    }
}

// NOTE: the word-store index above is convoluted; replaced by clean version:
__global__ void __launch_bounds__(64) scan1b_k(const float* __restrict__ th_p)
{
    const int idx = blockIdx.x * blockDim.x + threadIdx.x;
    const int b = idx >> 9;
    const int h = idx & 511;
    const float th = *th_p;
    const float inv = 1.0f / th;
    const float* zp = g_z1 + (size_t)b * Tt * Hh + h;
    uint32_t* bp = g_bits + (size_t)b * 16 * Hh + h;

    float cur[SCH], nxt[SCH];
    #pragma unroll
    for (int u = 0; u < SCH; u++) cur[u] = zp[(size_t)u * Hh];

    float m = 0.f;
    uint32_t word = 0;
    for (int t0 = 0; t0 < Tt; t0 += SCH) {
        if (t0 + SCH < Tt) {
            #pragma unroll
            for (int u = 0; u < SCH; u++) nxt[u] = zp[(size_t)(t0 + SCH + u) * Hh];
        }
        #pragma unroll
        for (int u = 0; u < SCH; u++) {
            m = m + cur[u];
            const float thr = __fmaf_rn(m, inv, -1.0f);
            if (thr >= 0.0f) word |= (1u << ((t0 + u) & 31));
            m = (thr > 0.0f) ? (m - th) : m;
        }
        if (((t0 + SCH) & 31) == 0) {
            bp[(size_t)((t0 + SCH - 32) >> 5) * Hh] = word;
            word = 0;
        }
        #pragma unroll
        for (int u = 0; u < SCH; u++) cur[u] = nxt[u];
    }
}

// -------- listify: per-row ascending-k index lists from bit matrix --------
__global__ void __launch_bounds__(256) listify_k()
{
    const int row  = blockIdx.x * 8 + (threadIdx.x >> 5);
    const int lane = threadIdx.x & 31;
    const int g32 = row >> 5, bitpos = row & 31;
    const uint32_t* wp = g_bits + (size_t)g32 * Hh + lane * 16;

    uint32_t mybits = 0;                        // 16 bits, ascending k from LSB
    #pragma unroll
    for (int i = 0; i < 16; i++) mybits |= ((wp[i] >> bitpos) & 1u) << i;

    const int c = __popc(mybits);
    int incl = c;
    #pragma unroll
    for (int d = 1; d < 32; d <<= 1) {
        int v = __shfl_up_sync(0xFFFFFFFFu, incl, d);
        if (lane >= d) incl += v;
    }
    int off = incl - c;
    const int total = __shfl_sync(0xFFFFFFFFu, incl, 31);

    uint16_t* lst = g_list + (size_t)row * 512;
    const int kbase = lane * 16;
    uint32_t bits = mybits;
    while (bits) {
        const int i = __ffs(bits) - 1;
        bits &= bits - 1;
        lst[off++] = (uint16_t)(kbase + i);
    }
    if (lane == 0) g_cnt[row] = total;
}

// -------- sparse GEMM2: y2[m,n] = serial ascending-k sum of W2T[k][n] over active k --------
// Bitwise identical to dense fma(s,w,acc): skipped terms add exactly +/-0.
__global__ void __launch_bounds__(128) sgemm2_sparse_k()
{
    const int m0 = blockIdx.x * 16;
    const int n  = (threadIdx.x >> 5) * 128 + (threadIdx.x & 31) * 4;

    for (int r = 0; r < 16; r++) {
        const int m = m0 + r;
        const int c = g_cnt[m];
        const uint16_t* lst = g_list + (size_t)m * 512;
        float4 acc = make_float4(0.f, 0.f, 0.f, 0.f);

        int j = 0;
        for (; j + 4 <= c; j += 4) {
            const ushort4 k4 = *(const ushort4*)(lst + j);   // uniform 8B load
            const float4 w0 = *(const float4*)&g_W2T[(size_t)k4.x * Hh + n];
            const float4 w1 = *(const float4*)&g_W2T[(size_t)k4.y * Hh + n];
            const float4 w2 = *(const float4*)&g_W2T[(size_t)k4.z * Hh + n];
            const float4 w3 = *(const float4*)&g_W2T[(size_t)k4.w * Hh + n];
            acc.x += w0.x; acc.y += w0.y; acc.z += w0.z; acc.w += w0.w;
            acc.x += w1.x; acc.y += w1.y; acc.z += w1.z; acc.w += w1.w;
            acc.x += w2.x; acc.y += w2.y; acc.z += w2.z; acc.w += w2.w;
            acc.x += w3.x; acc.y += w3.y; acc.z += w3.z; acc.w += w3.w;
        }
        for (; j < c; j++) {
            const int k = lst[j];
            const float4 w = *(const float4*)&g_W2T[(size_t)k * Hh + n];
            acc.x += w.x; acc.y += w.y; acc.z += w.z; acc.w += w.w;
        }
        *(float4*)&g_y2[(size_t)m * Hh + n] = acc;
    }
}

// -------- scan2: LIF with per-step bias in ref order --------
__global__ void __launch_bounds__(64) scan2_k(const float* __restrict__ th_p,
                                              const float* __restrict__ bias,
                                              float* __restrict__ out)
{
    const int idx = blockIdx.x * blockDim.x + threadIdx.x;
    const int b = idx >> 9;
    const int h = idx & 511;
    const float th = *th_p;
    const float bi = bias[h];
    const float inv = 1.0f / th;
    const float* yp = g_y2 + (size_t)b * Tt * Hh + h;
    float*       sp = out  + (size_t)b * Tt * Hh + h;

    float cur[SCH], nxt[SCH];
    #pragma unroll
    for (int u = 0; u < SCH; u++) cur[u] = yp[(size_t)u * Hh];

    float m = 0.f;
    for (int t0 = 0; t0 < Tt; t0 += SCH) {
        if (t0 + SCH < Tt) {
            #pragma unroll
            for (int u = 0; u < SCH; u++) nxt[u] = yp[(size_t)(t0 + SCH + u) * Hh];
        }
        #pragma unroll
        for (int u = 0; u < SCH; u++) {
            m = (m + cur[u]) + bi;                 // ((m + dot) + b) — ref order
            const float thr = __fmaf_rn(m, inv, -1.0f);
            sp[(size_t)(t0 + u) * Hh] = (thr >= 0.0f) ? 1.0f : 0.0f;
            m = (thr > 0.0f) ? (m - th) : m;
        }
        #pragma unroll
        for (int u = 0; u < SCH; u++) cur[u] = nxt[u];
    }
}

extern "C" void kernel_launch(void* const* d_in, const int* in_sizes, int n_in,
                              void* d_out, int out_size)
{
    const float* x   = (const float*)d_in[0];
    const float* c1w = (const float*)d_in[1];
    const float* c1b = (const float*)d_in[2];
    const float* c2w = (const float*)d_in[3];
    const float* c2b = (const float*)d_in[4];
    const float* th1 = (const float*)d_in[5];
    const float* th2 = (const float*)d_in[6];
    float* out = (float*)d_out;

    extract1_k<<<(Hh*Ii + 255)/256, 256>>>(c1w);
    {
        dim3 bt(32, 32);
        dim3 gt(Hh/32, Hh/32);
        extract2t_k<<<gt, bt>>>(c2w);
    }

    dim3 g1(Hh/128, Mm/128);              // (4, 256)
    sgemm1_k<<<g1, 256>>>(x, c1b);
    scan1b_k<<<Mm/64, 64>>>(th1);
    listify_k<<<Mm/8, 256>>>();
    sgemm2_sparse_k<<<Mm/16, 128>>>();
    scan2_k<<<Mm/64, 64>>>(th2, c2b, out);
}